// round 11
// baseline (speedup 1.0000x reference)
#include <cuda_runtime.h>
#include <cuda_bf16.h>
#include <mma.h>
#include <math.h>

using namespace nvcuda;

#define B_SZ   16384
#define F_INN  640
#define H1D    1024
#define H2D    512
#define T1D    256
#define T2D    128
#define DNUM   8

// scratch (allocations forbidden; __device__ globals are the sanctioned path)
// bf16 stored as ushort to avoid any static-init concerns
__device__ unsigned short g_xb [B_SZ * F_INN];   // 21 MB  bf16(x)
__device__ unsigned short g_w1b[F_INN * H1D];    // 1.3 MB bf16(W1)
__device__ unsigned short g_h1b[B_SZ * H1D];     // 33 MB  bf16(relu layer1)
__device__ unsigned short g_w2b[H1D * H2D];      // 1 MB   bf16(W2)
__device__ float          g_h2 [B_SZ * H2D];     // 32 MB  fp32 layer2 out
__device__ int   g_cnt[DNUM];
__device__ int   g_off[DNUM + 1];
__device__ int   g_cur[DNUM];
__device__ int   g_perm[B_SZ];

// ---------------------------------------------------------------------------
// fp32 -> bf16 conversion, vectorized (n divisible by 4)
// ---------------------------------------------------------------------------
__global__ void f2bf(const float4* __restrict__ in,
                     __nv_bfloat162* __restrict__ out, int n4)
{
    int i = blockIdx.x * blockDim.x + threadIdx.x;
    if (i < n4) {
        float4 v = in[i];
        out[2 * i]     = __nv_bfloat162(__float2bfloat16_rn(v.x),
                                        __float2bfloat16_rn(v.y));
        out[2 * i + 1] = __nv_bfloat162(__float2bfloat16_rn(v.z),
                                        __float2bfloat16_rn(v.w));
    }
}

// ---------------------------------------------------------------------------
// WMMA bf16 GEMM: C = relu(A @ B + bias)
// A[M,K] bf16 row-major, B[K,N] bf16 row-major, bias fp32, C OutT (bf16/fp32)
// Block tile 128x128, BK=16, 256 threads = 8 warps, warp tile 64x32 (4x2 wmma)
// Register-prefetch double buffering. K,N multiples of 16; M multiple of 128.
// Epilogue stages accumulators through smem (layout-agnostic), then bias+relu.
// dyn smem: max(As 6144 + Bs 4352, Cs 128*132*4 = 67584) = 67584 bytes
// ---------------------------------------------------------------------------
template <typename OutT>
__global__ __launch_bounds__(256) void gemm_wmma(
    int M, int N, int K,
    const __nv_bfloat16* __restrict__ A,
    const __nv_bfloat16* __restrict__ B,
    const float* __restrict__ bias,
    OutT* __restrict__ C)
{
    extern __shared__ char sm[];
    __nv_bfloat16* As = (__nv_bfloat16*)sm;            // [128][24]  (pad 8)
    __nv_bfloat16* Bs = (__nv_bfloat16*)(sm + 6144);   // [16][136]  (pad 8)
    float*         Cs = (float*)sm;                    // [128][132] (pad 4)

    const int tid = threadIdx.x;
    const int wid = tid >> 5;
    const int wr  = wid >> 2;                          // 0..1  (64-row slab)
    const int wc  = wid & 3;                           // 0..3  (32-col slab)

    const __nv_bfloat16* Ag = A + (size_t)blockIdx.y * 128 * K;
    const __nv_bfloat16* Bg = B + blockIdx.x * 128;

    // loaders: 256 threads cover A 128x16 and B 16x128 exactly (uint4 = 8 bf16)
    const int ar = tid >> 1, ac = (tid & 1) * 8;
    const int br = tid >> 4, bc = (tid & 15) * 8;

    wmma::fragment<wmma::accumulator, 16, 16, 16, float> acc[4][2];
    #pragma unroll
    for (int i = 0; i < 4; i++)
        #pragma unroll
        for (int j = 0; j < 2; j++)
            wmma::fill_fragment(acc[i][j], 0.0f);

    uint4 pa = *(const uint4*)(Ag + (size_t)ar * K + ac);
    uint4 pb = *(const uint4*)(Bg + (size_t)br * N + bc);
    *(uint4*)(As + ar * 24 + ac)  = pa;
    *(uint4*)(Bs + br * 136 + bc) = pb;

    for (int k0 = 0; k0 < K; k0 += 16) {
        __syncthreads();
        const bool more = (k0 + 16) < K;
        if (more) {
            pa = *(const uint4*)(Ag + (size_t)ar * K + (k0 + 16) + ac);
            pb = *(const uint4*)(Bg + (size_t)(k0 + 16 + br) * N + bc);
        }

        wmma::fragment<wmma::matrix_b, 16, 16, 16, __nv_bfloat16,
                       wmma::row_major> bf[2];
        #pragma unroll
        for (int j = 0; j < 2; j++)
            wmma::load_matrix_sync(bf[j], Bs + wc * 32 + j * 16, 136);

        #pragma unroll
        for (int i = 0; i < 4; i++) {
            wmma::fragment<wmma::matrix_a, 16, 16, 16, __nv_bfloat16,
                           wmma::row_major> af;
            wmma::load_matrix_sync(af, As + (wr * 64 + i * 16) * 24, 24);
            #pragma unroll
            for (int j = 0; j < 2; j++)
                wmma::mma_sync(acc[i][j], af, bf[j], acc[i][j]);
        }
        __syncthreads();
        if (more) {
            *(uint4*)(As + ar * 24 + ac)  = pa;
            *(uint4*)(Bs + br * 136 + bc) = pb;
        }
    }

    // epilogue: accumulators -> smem (API-owned layout), then bias+relu+store
    #pragma unroll
    for (int i = 0; i < 4; i++)
        #pragma unroll
        for (int j = 0; j < 2; j++)
            wmma::store_matrix_sync(
                Cs + (size_t)(wr * 64 + i * 16) * 132 + wc * 32 + j * 16,
                acc[i][j], 132, wmma::mem_row_major);
    __syncthreads();

    const int colBase = blockIdx.x * 128;
    for (int idx = tid; idx < 128 * 32; idx += 256) {
        const int row = idx >> 5;
        const int c4  = (idx & 31) << 2;
        float4 v  = *(float4*)(Cs + row * 132 + c4);
        float4 bv = *(const float4*)(bias + colBase + c4);
        v.x = fmaxf(v.x + bv.x, 0.f);
        v.y = fmaxf(v.y + bv.y, 0.f);
        v.z = fmaxf(v.z + bv.z, 0.f);
        v.w = fmaxf(v.w + bv.w, 0.f);
        const size_t o = (size_t)(blockIdx.y * 128 + row) * N + colBase + c4;
        if constexpr (sizeof(OutT) == 2) {
            __nv_bfloat162* p = (__nv_bfloat162*)((__nv_bfloat16*)C + o);
            p[0] = __nv_bfloat162(__float2bfloat16_rn(v.x),
                                  __float2bfloat16_rn(v.y));
            p[1] = __nv_bfloat162(__float2bfloat16_rn(v.z),
                                  __float2bfloat16_rn(v.w));
        } else {
            *(float4*)((float*)C + o) = v;
        }
    }
}

// ---------------------------------------------------------------------------
// Domain grouping: histogram -> scan -> scatter (per-sample math independent,
// so within-domain order doesn't affect the output)
// ---------------------------------------------------------------------------
__global__ void k_zero()
{
    int t = threadIdx.x;
    if (t < DNUM) { g_cnt[t] = 0; g_cur[t] = 0; }
}

__global__ void k_count(const int* __restrict__ dom)
{
    int i = blockIdx.x * blockDim.x + threadIdx.x;
    if (i < B_SZ) atomicAdd(&g_cnt[dom[i]], 1);
}

__global__ void k_scan()
{
    int o = 0;
    g_off[0] = 0;
    for (int d = 0; d < DNUM; d++) { o += g_cnt[d]; g_off[d + 1] = o; }
}

__global__ void k_scatter(const int* __restrict__ dom)
{
    int i = blockIdx.x * blockDim.x + threadIdx.x;
    if (i < B_SZ) {
        int d = dom[i];
        int pos = g_off[d] + atomicAdd(&g_cur[d], 1);
        g_perm[pos] = i;
    }
}

// ---------------------------------------------------------------------------
// Tower kernel: one block = 32 same-domain samples, 256 threads, fp32.
// dyn smem: h2 32*512 + t1 32*256 + t2 32*128 floats = 112 KB
// ---------------------------------------------------------------------------
__global__ __launch_bounds__(256) void tower_kernel(
    const float* __restrict__ TW1, const float* __restrict__ Tb1,
    const float* __restrict__ TW2, const float* __restrict__ Tb2,
    const float* __restrict__ TWo, const float* __restrict__ Tbo,
    float* __restrict__ out)
{
    extern __shared__ float smem[];
    float* h2s = smem;                 // 32*512
    float* t1s = smem + 32 * 512;      // 32*256
    float* t2s = t1s + 32 * 256;       // 32*128

    const int d     = blockIdx.y;
    const int start = g_off[d] + blockIdx.x * 32;
    const int end   = g_off[d + 1];
    if (start >= end) return;
    const int n   = min(32, end - start);
    const int tid = threadIdx.x;

    for (int i = tid; i < n * 128; i += 256) {
        int s = i >> 7, c = i & 127;
        ((float4*)h2s)[s * 128 + c] =
            ((const float4*)(g_h2 + (size_t)g_perm[start + s] * H2D))[c];
    }
    __syncthreads();

    // ---- phase 1: t1 = relu(h2 @ TW1[d] + Tb1[d]) ----
    {
        const float* w = TW1 + (size_t)d * H2D * T1D;
        float acc[32];
        const float b = Tb1[d * T1D + tid];
        #pragma unroll
        for (int s = 0; s < 32; s++) acc[s] = b;

        for (int k = 0; k < H2D; k += 4) {
            const float w0 = w[(k + 0) * T1D + tid];
            const float w1 = w[(k + 1) * T1D + tid];
            const float w2 = w[(k + 2) * T1D + tid];
            const float w3 = w[(k + 3) * T1D + tid];
            #pragma unroll
            for (int s = 0; s < 32; s++) {
                float4 h = ((const float4*)h2s)[s * 128 + (k >> 2)];
                acc[s] = fmaf(h.x, w0,
                         fmaf(h.y, w1,
                         fmaf(h.z, w2,
                         fmaf(h.w, w3, acc[s]))));
            }
        }
        #pragma unroll
        for (int s = 0; s < 32; s++)
            t1s[s * 256 + tid] = fmaxf(acc[s], 0.f);
    }
    __syncthreads();

    // ---- phase 2: t2 = relu(t1 @ TW2[d] + Tb2[d]) ----
    {
        const float* w = TW2 + (size_t)d * T1D * T2D;
        const int j  = tid & 127;
        const int sh = (tid >> 7) * 16;
        float acc[16];
        const float b = Tb2[d * T2D + j];
        #pragma unroll
        for (int i = 0; i < 16; i++) acc[i] = b;

        for (int k = 0; k < T1D; k += 4) {
            const float w0 = w[(k + 0) * T2D + j];
            const float w1 = w[(k + 1) * T2D + j];
            const float w2 = w[(k + 2) * T2D + j];
            const float w3 = w[(k + 3) * T2D + j];
            #pragma unroll
            for (int i = 0; i < 16; i++) {
                float4 t = ((const float4*)t1s)[(sh + i) * 64 + (k >> 2)];
                acc[i] = fmaf(t.x, w0,
                         fmaf(t.y, w1,
                         fmaf(t.z, w2,
                         fmaf(t.w, w3, acc[i]))));
            }
        }
        #pragma unroll
        for (int i = 0; i < 16; i++)
            t2s[(sh + i) * 128 + j] = fmaxf(acc[i], 0.f);
    }
    __syncthreads();

    // ---- phase 3: logit + sigmoid ----
    {
        const float* wo = TWo + (size_t)d * T2D;
        const int s  = tid >> 3;
        const int l8 = tid & 7;
        float p = 0.f;
        const int kb = l8 * 16;
        #pragma unroll
        for (int k = 0; k < 16; k++)
            p = fmaf(t2s[s * 128 + kb + k], wo[kb + k], p);
        p += __shfl_xor_sync(0xffffffffu, p, 1);
        p += __shfl_xor_sync(0xffffffffu, p, 2);
        p += __shfl_xor_sync(0xffffffffu, p, 4);
        if (l8 == 0 && s < n) {
            float logit = p + Tbo[d];
            out[g_perm[start + s]] = 1.f / (1.f + expf(-logit));
        }
    }
}

// ---------------------------------------------------------------------------
// launch
// ---------------------------------------------------------------------------
extern "C" void kernel_launch(void* const* d_in, const int* in_sizes, int n_in,
                              void* d_out, int out_size)
{
    const float* x    = (const float*)d_in[0];
    const int*   dom  = (const int*)  d_in[1];
    const float* W1   = (const float*)d_in[2];
    const float* b1   = (const float*)d_in[3];
    const float* W2   = (const float*)d_in[4];
    const float* b2   = (const float*)d_in[5];
    const float* TW1  = (const float*)d_in[6];
    const float* Tb1  = (const float*)d_in[7];
    const float* TW2  = (const float*)d_in[8];
    const float* Tb2  = (const float*)d_in[9];
    const float* TWo  = (const float*)d_in[10];
    const float* Tbo  = (const float*)d_in[11];
    float* out = (float*)d_out;

    // symbol addresses fetched every call (no static caching — harness rule)
    void *xb, *w1b, *h1b, *w2b, *h2p;
    cudaGetSymbolAddress(&xb,  g_xb);
    cudaGetSymbolAddress(&w1b, g_w1b);
    cudaGetSymbolAddress(&h1b, g_h1b);
    cudaGetSymbolAddress(&w2b, g_w2b);
    cudaGetSymbolAddress(&h2p, g_h2);

    cudaFuncSetAttribute(gemm_wmma<__nv_bfloat16>,
                         cudaFuncAttributeMaxDynamicSharedMemorySize, 67584);
    cudaFuncSetAttribute(gemm_wmma<float>,
                         cudaFuncAttributeMaxDynamicSharedMemorySize, 67584);
    cudaFuncSetAttribute(tower_kernel,
                         cudaFuncAttributeMaxDynamicSharedMemorySize, 114688);

    // grouping bookkeeping (tiny)
    k_zero<<<1, 32>>>();
    k_count<<<B_SZ / 256, 256>>>(dom);
    k_scan<<<1, 1>>>();
    k_scatter<<<B_SZ / 256, 256>>>(dom);

    // fp32 -> bf16 conversions
    f2bf<<<(B_SZ * F_INN / 4 + 255) / 256, 256>>>(
        (const float4*)x, (__nv_bfloat162*)xb, B_SZ * F_INN / 4);
    f2bf<<<(F_INN * H1D / 4 + 255) / 256, 256>>>(
        (const float4*)W1, (__nv_bfloat162*)w1b, F_INN * H1D / 4);
    f2bf<<<(H1D * H2D / 4 + 255) / 256, 256>>>(
        (const float4*)W2, (__nv_bfloat162*)w2b, H1D * H2D / 4);

    // bottom MLP on tensor cores (bf16 in, fp32 accumulate)
    gemm_wmma<__nv_bfloat16><<<dim3(H1D / 128, B_SZ / 128), 256, 67584>>>(
        B_SZ, H1D, F_INN,
        (const __nv_bfloat16*)xb, (const __nv_bfloat16*)w1b, b1,
        (__nv_bfloat16*)h1b);
    gemm_wmma<float><<<dim3(H2D / 128, B_SZ / 128), 256, 67584>>>(
        B_SZ, H2D, H1D,
        (const __nv_bfloat16*)h1b, (const __nv_bfloat16*)w2b, b2,
        (float*)h2p);

    // per-domain towers (only the selected domain per sample), fp32
    tower_kernel<<<dim3(512, DNUM), 256, 114688>>>(
        TW1, Tb1, TW2, Tb2, TWo, Tbo, out);
}

// round 15
// speedup vs baseline: 1.5593x; 1.5593x over previous
#include <cuda_runtime.h>
#include <cuda_bf16.h>
#include <mma.h>
#include <math.h>

using namespace nvcuda;

#define B_SZ   16384
#define F_INN  640
#define H1D    1024
#define H2D    512
#define T1D    256
#define T2D    128
#define DNUM   8
#define CAP    16384   // per-domain bucket capacity (worst case = B_SZ)

// scratch (__device__ globals — the sanctioned allocation-free path)
__device__ unsigned short g_xb  [B_SZ * F_INN];        // bf16(x)
__device__ unsigned short g_w1b [F_INN * H1D];         // bf16(W1)
__device__ unsigned short g_h1b [B_SZ * H1D];          // bf16(layer1 out)
__device__ unsigned short g_w2b [H1D * H2D];           // bf16(W2)
__device__ unsigned short g_tw1b[DNUM * H2D * T1D];    // bf16(TW1)
__device__ unsigned short g_tw2b[DNUM * T1D * T2D];    // bf16(TW2)
__device__ unsigned short g_h2p [(size_t)DNUM * CAP * H2D]; // bucketed bf16 h2
__device__ unsigned short g_t1  [(size_t)DNUM * CAP * T1D]; // bucketed bf16 t1
__device__ float          g_t2  [(size_t)DNUM * CAP * T2D]; // bucketed fp32 t2
__device__ int g_cur [DNUM];
__device__ int g_perm[DNUM * CAP];   // bucket row -> original sample
__device__ int g_rank[B_SZ];         // original sample -> bucket row

// ---------------------------------------------------------------------------
// fp32 -> bf16 conversion, vectorized (n divisible by 4)
// ---------------------------------------------------------------------------
__global__ void f2bf(const float4* __restrict__ in,
                     __nv_bfloat162* __restrict__ out, int n4)
{
    int i = blockIdx.x * blockDim.x + threadIdx.x;
    if (i < n4) {
        float4 v = in[i];
        out[2 * i]     = __nv_bfloat162(__float2bfloat16_rn(v.x),
                                        __float2bfloat16_rn(v.y));
        out[2 * i + 1] = __nv_bfloat162(__float2bfloat16_rn(v.z),
                                        __float2bfloat16_rn(v.w));
    }
}

// ---------------------------------------------------------------------------
// bookkeeping: bucket scatter (per-sample output is position-independent, so
// atomic ordering does not affect the final output values)
// ---------------------------------------------------------------------------
__global__ void k_zero()
{
    if (threadIdx.x < DNUM) g_cur[threadIdx.x] = 0;
}

__global__ void k_scatter(const int* __restrict__ dom)
{
    int i = blockIdx.x * blockDim.x + threadIdx.x;
    if (i < B_SZ) {
        int d = dom[i];
        int p = atomicAdd(&g_cur[d], 1);
        g_perm[d * CAP + p] = i;
        g_rank[i] = d * CAP + p;
    }
}

// zero-fill pad rows (cnt .. round_up(cnt,128)) of the h2 buckets so boundary
// GEMM tiles compute on deterministic zeros
__global__ void k_zeropad()
{
    int d   = blockIdx.x;
    int n   = g_cur[d];
    int up  = min((n + 127) & ~127, CAP);
    int rows = up - n;
    // one h2 row = H2D bf16 = 1024 B = 64 uint4
    for (int idx = threadIdx.x; idx < rows * 64; idx += blockDim.x) {
        int r = n + idx / 64, q = idx % 64;
        ((uint4*)(g_h2p + ((size_t)d * CAP + r) * H2D))[q] =
            make_uint4(0, 0, 0, 0);
    }
}

// ---------------------------------------------------------------------------
// WMMA bf16 GEMM: C = relu(A @ B + bias)   (same body that passed in R11)
// Optional rank[]: epilogue row r is stored to row rank[r] (bucket scatter).
// ---------------------------------------------------------------------------
template <typename OutT>
__global__ __launch_bounds__(256) void gemm_wmma(
    int M, int N, int K,
    const __nv_bfloat16* __restrict__ A,
    const __nv_bfloat16* __restrict__ B,
    const float* __restrict__ bias,
    OutT* __restrict__ C,
    const int* __restrict__ rank)
{
    extern __shared__ char sm[];
    __nv_bfloat16* As = (__nv_bfloat16*)sm;            // [128][24]
    __nv_bfloat16* Bs = (__nv_bfloat16*)(sm + 6144);   // [16][136]
    float*         Cs = (float*)sm;                    // [128][132]

    const int tid = threadIdx.x;
    const int wid = tid >> 5;
    const int wr  = wid >> 2;
    const int wc  = wid & 3;

    const __nv_bfloat16* Ag = A + (size_t)blockIdx.y * 128 * K;
    const __nv_bfloat16* Bg = B + blockIdx.x * 128;

    const int ar = tid >> 1, ac = (tid & 1) * 8;
    const int br = tid >> 4, bc = (tid & 15) * 8;

    wmma::fragment<wmma::accumulator, 16, 16, 16, float> acc[4][2];
    #pragma unroll
    for (int i = 0; i < 4; i++)
        #pragma unroll
        for (int j = 0; j < 2; j++)
            wmma::fill_fragment(acc[i][j], 0.0f);

    uint4 pa = *(const uint4*)(Ag + (size_t)ar * K + ac);
    uint4 pb = *(const uint4*)(Bg + (size_t)br * N + bc);
    *(uint4*)(As + ar * 24 + ac)  = pa;
    *(uint4*)(Bs + br * 136 + bc) = pb;

    for (int k0 = 0; k0 < K; k0 += 16) {
        __syncthreads();
        const bool more = (k0 + 16) < K;
        if (more) {
            pa = *(const uint4*)(Ag + (size_t)ar * K + (k0 + 16) + ac);
            pb = *(const uint4*)(Bg + (size_t)(k0 + 16 + br) * N + bc);
        }

        wmma::fragment<wmma::matrix_b, 16, 16, 16, __nv_bfloat16,
                       wmma::row_major> bf[2];
        #pragma unroll
        for (int j = 0; j < 2; j++)
            wmma::load_matrix_sync(bf[j], Bs + wc * 32 + j * 16, 136);

        #pragma unroll
        for (int i = 0; i < 4; i++) {
            wmma::fragment<wmma::matrix_a, 16, 16, 16, __nv_bfloat16,
                           wmma::row_major> af;
            wmma::load_matrix_sync(af, As + (wr * 64 + i * 16) * 24, 24);
            #pragma unroll
            for (int j = 0; j < 2; j++)
                wmma::mma_sync(acc[i][j], af, bf[j], acc[i][j]);
        }
        __syncthreads();
        if (more) {
            *(uint4*)(As + ar * 24 + ac)  = pa;
            *(uint4*)(Bs + br * 136 + bc) = pb;
        }
    }

    #pragma unroll
    for (int i = 0; i < 4; i++)
        #pragma unroll
        for (int j = 0; j < 2; j++)
            wmma::store_matrix_sync(
                Cs + (size_t)(wr * 64 + i * 16) * 132 + wc * 32 + j * 16,
                acc[i][j], 132, wmma::mem_row_major);
    __syncthreads();

    const int colBase = blockIdx.x * 128;
    for (int idx = tid; idx < 128 * 32; idx += 256) {
        const int row = idx >> 5;
        const int c4  = (idx & 31) << 2;
        float4 v  = *(float4*)(Cs + row * 132 + c4);
        float4 bv = *(const float4*)(bias + colBase + c4);
        v.x = fmaxf(v.x + bv.x, 0.f);
        v.y = fmaxf(v.y + bv.y, 0.f);
        v.z = fmaxf(v.z + bv.z, 0.f);
        v.w = fmaxf(v.w + bv.w, 0.f);
        const int gRow = blockIdx.y * 128 + row;
        const size_t orow = rank ? (size_t)rank[gRow] : (size_t)gRow;
        const size_t o = orow * N + colBase + c4;
        if constexpr (sizeof(OutT) == 2) {
            __nv_bfloat162* p = (__nv_bfloat162*)((__nv_bfloat16*)C + o);
            p[0] = __nv_bfloat162(__float2bfloat16_rn(v.x),
                                  __float2bfloat16_rn(v.y));
            p[1] = __nv_bfloat162(__float2bfloat16_rn(v.z),
                                  __float2bfloat16_rn(v.w));
        } else {
            *(float4*)((float*)C + o) = v;
        }
    }
}

// ---------------------------------------------------------------------------
// Bucketed per-domain WMMA GEMM: same body, 3D grid (x=N-blk, y=M-blk, z=dom),
// early exit on the domain's live row count.
// ---------------------------------------------------------------------------
template <typename OutT>
__global__ __launch_bounds__(256) void gemm_wmma_bkt(
    int N, int K,
    const __nv_bfloat16* __restrict__ Abase,
    const __nv_bfloat16* __restrict__ Bbase,
    const float* __restrict__ biasBase,
    OutT* __restrict__ Cbase)
{
    const int d   = blockIdx.z;
    const int cnt = g_cur[d];
    if ((int)(blockIdx.y * 128) >= cnt) return;

    extern __shared__ char sm[];
    __nv_bfloat16* As = (__nv_bfloat16*)sm;
    __nv_bfloat16* Bs = (__nv_bfloat16*)(sm + 6144);
    float*         Cs = (float*)sm;

    const int tid = threadIdx.x;
    const int wid = tid >> 5;
    const int wr  = wid >> 2;
    const int wc  = wid & 3;

    const __nv_bfloat16* Ag = Abase + (size_t)d * CAP * K
                                    + (size_t)blockIdx.y * 128 * K;
    const __nv_bfloat16* Bg = Bbase + (size_t)d * K * N + blockIdx.x * 128;
    const float* bias = biasBase + d * N;
    OutT* C = Cbase + (size_t)d * CAP * N;

    const int ar = tid >> 1, ac = (tid & 1) * 8;
    const int br = tid >> 4, bc = (tid & 15) * 8;

    wmma::fragment<wmma::accumulator, 16, 16, 16, float> acc[4][2];
    #pragma unroll
    for (int i = 0; i < 4; i++)
        #pragma unroll
        for (int j = 0; j < 2; j++)
            wmma::fill_fragment(acc[i][j], 0.0f);

    uint4 pa = *(const uint4*)(Ag + (size_t)ar * K + ac);
    uint4 pb = *(const uint4*)(Bg + (size_t)br * N + bc);
    *(uint4*)(As + ar * 24 + ac)  = pa;
    *(uint4*)(Bs + br * 136 + bc) = pb;

    for (int k0 = 0; k0 < K; k0 += 16) {
        __syncthreads();
        const bool more = (k0 + 16) < K;
        if (more) {
            pa = *(const uint4*)(Ag + (size_t)ar * K + (k0 + 16) + ac);
            pb = *(const uint4*)(Bg + (size_t)(k0 + 16 + br) * N + bc);
        }

        wmma::fragment<wmma::matrix_b, 16, 16, 16, __nv_bfloat16,
                       wmma::row_major> bf[2];
        #pragma unroll
        for (int j = 0; j < 2; j++)
            wmma::load_matrix_sync(bf[j], Bs + wc * 32 + j * 16, 136);

        #pragma unroll
        for (int i = 0; i < 4; i++) {
            wmma::fragment<wmma::matrix_a, 16, 16, 16, __nv_bfloat16,
                           wmma::row_major> af;
            wmma::load_matrix_sync(af, As + (wr * 64 + i * 16) * 24, 24);
            #pragma unroll
            for (int j = 0; j < 2; j++)
                wmma::mma_sync(acc[i][j], af, bf[j], acc[i][j]);
        }
        __syncthreads();
        if (more) {
            *(uint4*)(As + ar * 24 + ac)  = pa;
            *(uint4*)(Bs + br * 136 + bc) = pb;
        }
    }

    #pragma unroll
    for (int i = 0; i < 4; i++)
        #pragma unroll
        for (int j = 0; j < 2; j++)
            wmma::store_matrix_sync(
                Cs + (size_t)(wr * 64 + i * 16) * 132 + wc * 32 + j * 16,
                acc[i][j], 132, wmma::mem_row_major);
    __syncthreads();

    const int colBase = blockIdx.x * 128;
    for (int idx = tid; idx < 128 * 32; idx += 256) {
        const int row = idx >> 5;
        const int c4  = (idx & 31) << 2;
        float4 v  = *(float4*)(Cs + row * 132 + c4);
        float4 bv = *(const float4*)(bias + colBase + c4);
        v.x = fmaxf(v.x + bv.x, 0.f);
        v.y = fmaxf(v.y + bv.y, 0.f);
        v.z = fmaxf(v.z + bv.z, 0.f);
        v.w = fmaxf(v.w + bv.w, 0.f);
        const size_t o = ((size_t)blockIdx.y * 128 + row) * N + colBase + c4;
        if constexpr (sizeof(OutT) == 2) {
            __nv_bfloat162* p = (__nv_bfloat162*)((__nv_bfloat16*)C + o);
            p[0] = __nv_bfloat162(__float2bfloat16_rn(v.x),
                                  __float2bfloat16_rn(v.y));
            p[1] = __nv_bfloat162(__float2bfloat16_rn(v.z),
                                  __float2bfloat16_rn(v.w));
        } else {
            *(float4*)((float*)C + o) = v;
        }
    }
}

// ---------------------------------------------------------------------------
// final logit + sigmoid: one warp per bucketed sample, scatter to out[orig]
// ---------------------------------------------------------------------------
__global__ void k_logit(const float* __restrict__ TWo,
                        const float* __restrict__ Tbo,
                        float* __restrict__ out)
{
    int w    = (blockIdx.x * blockDim.x + threadIdx.x) >> 5;
    int lane = threadIdx.x & 31;
    int d = w / CAP, i = w % CAP;
    if (i >= g_cur[d]) return;
    size_t row = (size_t)d * CAP + i;
    const float* t2r = g_t2 + row * T2D;
    const float* wo  = TWo + d * T2D;
    float p = 0.f;
    #pragma unroll
    for (int k = 0; k < 4; k++)
        p = fmaf(t2r[lane + 32 * k], wo[lane + 32 * k], p);
    #pragma unroll
    for (int off = 16; off; off >>= 1)
        p += __shfl_xor_sync(0xffffffffu, p, off);
    if (lane == 0)
        out[g_perm[row]] = 1.f / (1.f + expf(-(p + Tbo[d])));
}

// ---------------------------------------------------------------------------
// launch
// ---------------------------------------------------------------------------
extern "C" void kernel_launch(void* const* d_in, const int* in_sizes, int n_in,
                              void* d_out, int out_size)
{
    const float* x    = (const float*)d_in[0];
    const int*   dom  = (const int*)  d_in[1];
    const float* W1   = (const float*)d_in[2];
    const float* b1   = (const float*)d_in[3];
    const float* W2   = (const float*)d_in[4];
    const float* b2   = (const float*)d_in[5];
    const float* TW1  = (const float*)d_in[6];
    const float* Tb1  = (const float*)d_in[7];
    const float* TW2  = (const float*)d_in[8];
    const float* Tb2  = (const float*)d_in[9];
    const float* TWo  = (const float*)d_in[10];
    const float* Tbo  = (const float*)d_in[11];
    float* out = (float*)d_out;

    void *xb, *w1b, *h1b, *w2b, *tw1b, *tw2b, *h2p, *t1, *t2, *rk;
    cudaGetSymbolAddress(&xb,   g_xb);
    cudaGetSymbolAddress(&w1b,  g_w1b);
    cudaGetSymbolAddress(&h1b,  g_h1b);
    cudaGetSymbolAddress(&w2b,  g_w2b);
    cudaGetSymbolAddress(&tw1b, g_tw1b);
    cudaGetSymbolAddress(&tw2b, g_tw2b);
    cudaGetSymbolAddress(&h2p,  g_h2p);
    cudaGetSymbolAddress(&t1,   g_t1);
    cudaGetSymbolAddress(&t2,   g_t2);
    cudaGetSymbolAddress(&rk,   g_rank);

    cudaFuncSetAttribute(gemm_wmma<__nv_bfloat16>,
                         cudaFuncAttributeMaxDynamicSharedMemorySize, 67584);
    cudaFuncSetAttribute(gemm_wmma_bkt<__nv_bfloat16>,
                         cudaFuncAttributeMaxDynamicSharedMemorySize, 67584);
    cudaFuncSetAttribute(gemm_wmma_bkt<float>,
                         cudaFuncAttributeMaxDynamicSharedMemorySize, 67584);

    // bookkeeping
    k_zero<<<1, 32>>>();
    k_scatter<<<B_SZ / 256, 256>>>(dom);
    k_zeropad<<<DNUM, 256>>>();

    // fp32 -> bf16 conversions
    f2bf<<<(B_SZ * F_INN / 4 + 255) / 256, 256>>>(
        (const float4*)x, (__nv_bfloat162*)xb, B_SZ * F_INN / 4);
    f2bf<<<(F_INN * H1D / 4 + 255) / 256, 256>>>(
        (const float4*)W1, (__nv_bfloat162*)w1b, F_INN * H1D / 4);
    f2bf<<<(H1D * H2D / 4 + 255) / 256, 256>>>(
        (const float4*)W2, (__nv_bfloat162*)w2b, H1D * H2D / 4);
    f2bf<<<(DNUM * H2D * T1D / 4 + 255) / 256, 256>>>(
        (const float4*)TW1, (__nv_bfloat162*)tw1b, DNUM * H2D * T1D / 4);
    f2bf<<<(DNUM * T1D * T2D / 4 + 255) / 256, 256>>>(
        (const float4*)TW2, (__nv_bfloat162*)tw2b, DNUM * T1D * T2D / 4);

    // bottom MLP (tensor cores, fp32 accumulate)
    gemm_wmma<__nv_bfloat16><<<dim3(H1D / 128, B_SZ / 128), 256, 67584>>>(
        B_SZ, H1D, F_INN,
        (const __nv_bfloat16*)xb, (const __nv_bfloat16*)w1b, b1,
        (__nv_bfloat16*)h1b, nullptr);
    // layer 2: bf16 out, scattered into domain buckets via rank[]
    gemm_wmma<__nv_bfloat16><<<dim3(H2D / 128, B_SZ / 128), 256, 67584>>>(
        B_SZ, H2D, H1D,
        (const __nv_bfloat16*)h1b, (const __nv_bfloat16*)w2b, b2,
        (__nv_bfloat16*)h2p, (const int*)rk);

    // towers as bucketed per-domain GEMMs (tensor cores)
    gemm_wmma_bkt<__nv_bfloat16>
        <<<dim3(T1D / 128, CAP / 128, DNUM), 256, 67584>>>(
        T1D, H2D,
        (const __nv_bfloat16*)h2p, (const __nv_bfloat16*)tw1b, Tb1,
        (__nv_bfloat16*)t1);
    gemm_wmma_bkt<float>
        <<<dim3(T2D / 128, CAP / 128, DNUM), 256, 67584>>>(
        T2D, T1D,
        (const __nv_bfloat16*)t1, (const __nv_bfloat16*)tw2b, Tb2,
        (float*)t2);

    // final logits
    k_logit<<<DNUM * CAP / 8, 256>>>(TWo, Tbo, out);
}